// round 2
// baseline (speedup 1.0000x reference)
#include <cuda_runtime.h>
#include <cuda_bf16.h>

// Problem constants
#define BB 4
#define NN 2048
#define DD 1024
#define HH 16
#define DH 64
#define BN (BB*NN)          // 8192
#define LN_EPS 1e-5f

// Scratch (device globals; no allocation allowed)
__device__ float g_xn[BN * DD];          // LN(x)
__device__ float g_q [BB * HH * NN * DH];
__device__ float g_k [BB * HH * NN * DH];
__device__ float g_v [BB * HH * NN * DH];
__device__ float g_ao[BN * DD];          // attention output, [b,n,h*64+dh]
__device__ float g_maskbias[BB * NN];    // 0.0f (attend) or -1e30f (masked)

// ---------------------------------------------------------------------------
// Kernel 0: mask preprocessing. Detects whether the mask buffer is int32
// (one word per element) or byte-packed bool, then expands to float bias.
// Single block; reads only the first 8KB for detection (valid either way).
// ---------------------------------------------------------------------------
__global__ __launch_bounds__(256)
void mask_prep_kernel(const void* __restrict__ mask)
{
    __shared__ int s_packed;
    if (threadIdx.x == 0) s_packed = 0;
    __syncthreads();

    const unsigned* mw = (const unsigned*)mask;
    int bad = 0;
    for (int i = threadIdx.x; i < 2048; i += 256)
        if (mw[i] > 1u) bad = 1;
    if (bad) atomicOr(&s_packed, 1);
    __syncthreads();
    const bool packed = (s_packed != 0);

    const int* mi = (const int*)mask;
    const unsigned char* mb = (const unsigned char*)mask;
    for (int i = threadIdx.x; i < BB * NN; i += 256) {
        const int on = packed ? (int)mb[i] : mi[i];
        g_maskbias[i] = on ? 0.0f : -1e30f;
    }
}

// ---------------------------------------------------------------------------
// Kernel 1: row LayerNorm over D=1024.  grid=8192 blocks, 256 threads.
// ---------------------------------------------------------------------------
__global__ __launch_bounds__(256)
void ln_x_kernel(const float* __restrict__ x,
                 const float* __restrict__ w,
                 const float* __restrict__ b)
{
    __shared__ float red_s[8];
    __shared__ float red_q[8];
    __shared__ float stats[2];
    const int row = blockIdx.x;
    const int t = threadIdx.x;
    const int lane = t & 31, warp = t >> 5;

    const float* xr = x + (long)row * DD;
    float4 xv = *(const float4*)(xr + t * 4);
    float sum = xv.x + xv.y + xv.z + xv.w;
    float ssq = fmaf(xv.x, xv.x, fmaf(xv.y, xv.y, fmaf(xv.z, xv.z, xv.w * xv.w)));
    #pragma unroll
    for (int o = 16; o > 0; o >>= 1) {
        sum += __shfl_xor_sync(0xffffffffu, sum, o);
        ssq += __shfl_xor_sync(0xffffffffu, ssq, o);
    }
    if (lane == 0) { red_s[warp] = sum; red_q[warp] = ssq; }
    __syncthreads();
    if (warp == 0) {
        float a = (lane < 8) ? red_s[lane] : 0.0f;
        float c = (lane < 8) ? red_q[lane] : 0.0f;
        #pragma unroll
        for (int o = 4; o > 0; o >>= 1) {
            a += __shfl_xor_sync(0xffffffffu, a, o);
            c += __shfl_xor_sync(0xffffffffu, c, o);
        }
        if (lane == 0) { stats[0] = a * (1.0f / DD); stats[1] = c * (1.0f / DD); }
    }
    __syncthreads();
    const float mean = stats[0];
    const float var = stats[1] - mean * mean;
    const float rstd = rsqrtf(var + LN_EPS);

    float4 wv = *(const float4*)(w + t * 4);
    float4 bv = *(const float4*)(b + t * 4);
    float4 ov;
    ov.x = (xv.x - mean) * rstd * wv.x + bv.x;
    ov.y = (xv.y - mean) * rstd * wv.y + bv.y;
    ov.z = (xv.z - mean) * rstd * wv.z + bv.z;
    ov.w = (xv.w - mean) * rstd * wv.w + bv.w;
    *(float4*)(g_xn + (long)row * DD + t * 4) = ov;
}

// ---------------------------------------------------------------------------
// Kernel 2: SGEMM  C[8192,1024] = A[8192,1024] @ W[1024,1024]^T (+bias)
// 128x128 tile, K-tile 16, 256 threads, 8x8 microtile.
// MODE 0: A=g_ao, C=Cout (plain layout, no bias)   -- final projection
// MODE 1/2/3: A=g_xn, C=g_q/g_k/g_v scattered to [b,h,n,dh], + bias
// ---------------------------------------------------------------------------
template<int MODE>
__global__ __launch_bounds__(256)
void sgemm_kernel(const float* __restrict__ W,
                  const float* __restrict__ bias,
                  float* __restrict__ Cout)
{
    __shared__ __align__(16) float As[16][132];
    __shared__ __align__(16) float Bs[16][132];

    const float* A = (MODE == 0) ? g_ao : g_xn;
    float* C = (MODE == 1) ? g_q : (MODE == 2) ? g_k : (MODE == 3) ? g_v : Cout;

    const int t  = threadIdx.x;
    const int tx = t & 15;
    const int ty = t >> 4;
    const int bm = blockIdx.y << 7;
    const int bn = blockIdx.x << 7;

    float acc[8][8];
    #pragma unroll
    for (int i = 0; i < 8; i++)
        #pragma unroll
        for (int j = 0; j < 8; j++) acc[i][j] = 0.0f;

    const int lrow = t >> 2;          // 0..63
    const int lc4  = (t & 3) << 2;    // 0,4,8,12
    const float* Abase = A + (long)bm * DD;
    const float* Wbase = W + (long)bn * DD;

    for (int kt = 0; kt < DD; kt += 16) {
        #pragma unroll
        for (int i = 0; i < 2; i++) {
            const int row = lrow + (i << 6);
            float4 va = *(const float4*)(Abase + (long)row * DD + kt + lc4);
            As[lc4 + 0][row] = va.x;
            As[lc4 + 1][row] = va.y;
            As[lc4 + 2][row] = va.z;
            As[lc4 + 3][row] = va.w;
            float4 vb = *(const float4*)(Wbase + (long)row * DD + kt + lc4);
            Bs[lc4 + 0][row] = vb.x;
            Bs[lc4 + 1][row] = vb.y;
            Bs[lc4 + 2][row] = vb.z;
            Bs[lc4 + 3][row] = vb.w;
        }
        __syncthreads();
        #pragma unroll
        for (int k = 0; k < 16; k++) {
            float4 a0 = *(const float4*)&As[k][ty << 2];
            float4 a1 = *(const float4*)&As[k][64 + (ty << 2)];
            float4 b0 = *(const float4*)&Bs[k][tx << 2];
            float4 b1 = *(const float4*)&Bs[k][64 + (tx << 2)];
            float av[8] = {a0.x, a0.y, a0.z, a0.w, a1.x, a1.y, a1.z, a1.w};
            float bv[8] = {b0.x, b0.y, b0.z, b0.w, b1.x, b1.y, b1.z, b1.w};
            #pragma unroll
            for (int i = 0; i < 8; i++)
                #pragma unroll
                for (int j = 0; j < 8; j++)
                    acc[i][j] = fmaf(av[i], bv[j], acc[i][j]);
        }
        __syncthreads();
    }

    // Epilogue
    #pragma unroll
    for (int i = 0; i < 8; i++) {
        const int r = bm + ((i < 4) ? ((ty << 2) + i) : (64 + (ty << 2) + i - 4));
        #pragma unroll
        for (int j = 0; j < 8; j++) {
            const int c = bn + ((j < 4) ? ((tx << 2) + j) : (64 + (tx << 2) + j - 4));
            float val = acc[i][j];
            if (MODE == 0) {
                C[(long)r * DD + c] = val;
            } else {
                val += bias[c];
                const int h  = c >> 6;
                const int dh = c & 63;
                const int b_ = r >> 11;     // r / 2048
                const int n  = r & 2047;
                C[((((long)(b_ * HH + h)) * NN + n) << 6) + dh] = val;
            }
        }
    }
}

// ---------------------------------------------------------------------------
// Kernel 3: per-head LayerNorm over DH=64 (in-place on g_q / g_k).
// One warp per row; 8 rows per 256-thread block.
// ---------------------------------------------------------------------------
template<int WHICH>   // 1 = q (apply scale), 2 = k
__global__ __launch_bounds__(256)
void headln_kernel(const float* __restrict__ w,
                   const float* __restrict__ b,
                   float sc)
{
    float* base = (WHICH == 1) ? g_q : g_k;
    const int warp = threadIdx.x >> 5;
    const int lane = threadIdx.x & 31;
    const long row = (long)blockIdx.x * 8 + warp;
    float* p = base + row * DH;

    float2 xv = *(float2*)(p + lane * 2);
    float sum = xv.x + xv.y;
    float ssq = fmaf(xv.x, xv.x, xv.y * xv.y);
    #pragma unroll
    for (int o = 16; o > 0; o >>= 1) {
        sum += __shfl_xor_sync(0xffffffffu, sum, o);
        ssq += __shfl_xor_sync(0xffffffffu, ssq, o);
    }
    const float mean = sum * (1.0f / DH);
    const float var = ssq * (1.0f / DH) - mean * mean;
    const float rstd = rsqrtf(var + LN_EPS);

    float2 wv = *(const float2*)(w + lane * 2);
    float2 bv = *(const float2*)(b + lane * 2);
    float2 ov;
    ov.x = ((xv.x - mean) * rstd * wv.x + bv.x) * sc;
    ov.y = ((xv.y - mean) * rstd * wv.y + bv.y) * sc;
    *(float2*)(p + lane * 2) = ov;
}

// ---------------------------------------------------------------------------
// Kernel 4: flash attention, fp32.
// grid (N/128, H, B), 128 threads; each thread owns one query row.
// K/V staged in smem in 64-key tiles; online softmax in registers.
// ---------------------------------------------------------------------------
__global__ __launch_bounds__(128)
void attn_kernel()
{
    __shared__ __align__(16) float Ks[64 * 64];
    __shared__ __align__(16) float Vs[64 * 64];
    __shared__ float mb[64];

    const int t = threadIdx.x;
    const int b = blockIdx.z;
    const int h = blockIdx.y;
    const int n = blockIdx.x * 128 + t;

    const long head_off = ((long)(b * HH + h)) * NN;
    const float* qp = g_q + ((head_off + n) << 6);
    float qr[64];
    #pragma unroll
    for (int i = 0; i < 16; i++) {
        float4 tmp = *(const float4*)(qp + i * 4);
        qr[i * 4 + 0] = tmp.x; qr[i * 4 + 1] = tmp.y;
        qr[i * 4 + 2] = tmp.z; qr[i * 4 + 3] = tmp.w;
    }

    float acc[64];
    #pragma unroll
    for (int d = 0; d < 64; d++) acc[d] = 0.0f;
    float m = -1e30f, l = 0.0f;

    const float* kbase = g_k + (head_off << 6);
    const float* vbase = g_v + (head_off << 6);
    const float* mrow = g_maskbias + b * NN;

    for (int kt = 0; kt < NN; kt += 64) {
        const float* ksrc = kbase + ((long)kt << 6);
        const float* vsrc = vbase + ((long)kt << 6);
        #pragma unroll
        for (int i = 0; i < 8; i++) {
            const int f = t + i * 128;
            *(float4*)&Ks[f * 4] = *(const float4*)(ksrc + f * 4);
            *(float4*)&Vs[f * 4] = *(const float4*)(vsrc + f * 4);
        }
        if (t < 64) mb[t] = mrow[kt + t];
        __syncthreads();

        #pragma unroll 1
        for (int c = 0; c < 64; c += 8) {
            float s[8];
            #pragma unroll
            for (int j = 0; j < 8; j++) {
                const float* kj = &Ks[(c + j) * 64];
                float s0 = 0.0f, s1 = 0.0f, s2 = 0.0f, s3 = 0.0f;
                #pragma unroll
                for (int d = 0; d < 64; d += 4) {
                    float4 kv = *(const float4*)(kj + d);
                    s0 = fmaf(qr[d + 0], kv.x, s0);
                    s1 = fmaf(qr[d + 1], kv.y, s1);
                    s2 = fmaf(qr[d + 2], kv.z, s2);
                    s3 = fmaf(qr[d + 3], kv.w, s3);
                }
                s[j] = (s0 + s1) + (s2 + s3) + mb[c + j];
            }
            float cm = s[0];
            #pragma unroll
            for (int j = 1; j < 8; j++) cm = fmaxf(cm, s[j]);
            const float mnew = fmaxf(m, cm);
            const float scale = __expf(m - mnew);   // m==mnew==-1e30 -> exp(0)=1
            l *= scale;
            #pragma unroll
            for (int d = 0; d < 64; d++) acc[d] *= scale;
            #pragma unroll
            for (int j = 0; j < 8; j++) {
                const float p = __expf(s[j] - mnew);
                l += p;
                const float* vj = &Vs[(c + j) * 64];
                #pragma unroll
                for (int d = 0; d < 64; d += 4) {
                    float4 vv = *(const float4*)(vj + d);
                    acc[d + 0] = fmaf(p, vv.x, acc[d + 0]);
                    acc[d + 1] = fmaf(p, vv.y, acc[d + 1]);
                    acc[d + 2] = fmaf(p, vv.z, acc[d + 2]);
                    acc[d + 3] = fmaf(p, vv.w, acc[d + 3]);
                }
            }
            m = mnew;
        }
        __syncthreads();
    }

    const float inv = 1.0f / l;
    float* op = g_ao + ((long)(b * NN + n)) * DD + (h << 6);
    #pragma unroll
    for (int d = 0; d < 64; d += 4) {
        float4 o;
        o.x = acc[d + 0] * inv; o.y = acc[d + 1] * inv;
        o.z = acc[d + 2] * inv; o.w = acc[d + 3] * inv;
        *(float4*)(op + d) = o;
    }
}

// ---------------------------------------------------------------------------
// Launch
// ---------------------------------------------------------------------------
extern "C" void kernel_launch(void* const* d_in, const int* in_sizes, int n_in,
                              void* d_out, int out_size)
{
    const float* x       = (const float*)d_in[0];
    const void*  mask    = (const void*)d_in[1];
    const float* norm_w  = (const float*)d_in[2];
    const float* norm_b  = (const float*)d_in[3];
    const float* qn_w    = (const float*)d_in[4];
    const float* qn_b    = (const float*)d_in[5];
    const float* kn_w    = (const float*)d_in[6];
    const float* kn_b    = (const float*)d_in[7];
    const float* Wq      = (const float*)d_in[8];
    const float* bq      = (const float*)d_in[9];
    const float* Wk      = (const float*)d_in[10];
    const float* bk      = (const float*)d_in[11];
    const float* Wv      = (const float*)d_in[12];
    const float* bv      = (const float*)d_in[13];
    const float* Wo      = (const float*)d_in[14];
    float* out = (float*)d_out;

    // 0. Mask -> float bias (dtype-robust)
    mask_prep_kernel<<<1, 256>>>(mask);

    // 1. LN(x) -> g_xn
    ln_x_kernel<<<BN, 256>>>(x, norm_w, norm_b);

    // 2. QKV projections -> g_q/g_k/g_v in [b,h,n,dh]
    dim3 gg(DD / 128, BN / 128);   // (8, 64)
    sgemm_kernel<1><<<gg, 256>>>(Wq, bq, nullptr);
    sgemm_kernel<2><<<gg, 256>>>(Wk, bk, nullptr);
    sgemm_kernel<3><<<gg, 256>>>(Wv, bv, nullptr);

    // 3. Per-head LN (q scaled by DH^-0.5)
    const int ln_blocks = (BB * HH * NN) / 8;   // 16384
    headln_kernel<1><<<ln_blocks, 256>>>(qn_w, qn_b, 0.125f);
    headln_kernel<2><<<ln_blocks, 256>>>(kn_w, kn_b, 1.0f);

    // 4. Flash attention -> g_ao [b,n,d]
    attn_kernel<<<dim3(NN / 128, HH, BB), 128>>>();

    // 5. Output projection -> d_out
    sgemm_kernel<0><<<gg, 256>>>(Wo, nullptr, out);
}

// round 4
// speedup vs baseline: 1.2598x; 1.2598x over previous
#include <cuda_runtime.h>
#include <cuda_bf16.h>
#include <cstdint>

// Problem constants
#define BB 4
#define NN 2048
#define DD 1024
#define HH 16
#define DH 64
#define BN (BB*NN)          // 8192
#define LN_EPS 1e-5f

// ---------------------------------------------------------------------------
// Device scratch (no allocation allowed)
// ---------------------------------------------------------------------------
__device__ __nv_bfloat16 g_xn_hi[BN * DD];
__device__ __nv_bfloat16 g_xn_lo[BN * DD];
__device__ __nv_bfloat16 g_ao_hi[BN * DD];
__device__ __nv_bfloat16 g_ao_lo[BN * DD];
__device__ __nv_bfloat16 g_whi[4 * DD * DD];
__device__ __nv_bfloat16 g_wlo[4 * DD * DD];
__device__ float g_q[BB * HH * NN * DH];
__device__ float g_k[BB * HH * NN * DH];
__device__ float g_v[BB * HH * NN * DH];
__device__ float g_maskbias[BB * NN];

// ---------------------------------------------------------------------------
// Helpers
// ---------------------------------------------------------------------------
__device__ __forceinline__ uint32_t s2u(const void* p) {
    uint32_t a;
    asm("{ .reg .u64 t; cvta.to.shared.u64 t, %1; cvt.u32.u64 %0, t; }"
        : "=r"(a) : "l"(p));
    return a;
}

__device__ __forceinline__ void ldsm4(uint32_t& r0, uint32_t& r1,
                                      uint32_t& r2, uint32_t& r3,
                                      uint32_t addr) {
    asm volatile("ldmatrix.sync.aligned.m8n8.x4.shared.b16 {%0,%1,%2,%3}, [%4];"
                 : "=r"(r0), "=r"(r1), "=r"(r2), "=r"(r3) : "r"(addr));
}

__device__ __forceinline__ void mma16816(float* c, const uint32_t* a,
                                         uint32_t b0, uint32_t b1) {
    asm volatile(
        "mma.sync.aligned.m16n8k16.row.col.f32.bf16.bf16.f32 "
        "{%0,%1,%2,%3}, {%4,%5,%6,%7}, {%8,%9}, {%0,%1,%2,%3};"
        : "+f"(c[0]), "+f"(c[1]), "+f"(c[2]), "+f"(c[3])
        : "r"(a[0]), "r"(a[1]), "r"(a[2]), "r"(a[3]), "r"(b0), "r"(b1));
}

// hi/lo bf16 split store of 4 consecutive floats
__device__ __forceinline__ void hl4_store(float4 v, __nv_bfloat16* hip,
                                          __nv_bfloat16* lop) {
    __nv_bfloat162 h0 = __float22bfloat162_rn(make_float2(v.x, v.y));
    __nv_bfloat162 h1 = __float22bfloat162_rn(make_float2(v.z, v.w));
    float2 f0 = __bfloat1622float2(h0);
    float2 f1 = __bfloat1622float2(h1);
    __nv_bfloat162 l0 = __float22bfloat162_rn(make_float2(v.x - f0.x, v.y - f0.y));
    __nv_bfloat162 l1 = __float22bfloat162_rn(make_float2(v.z - f1.x, v.w - f1.y));
    *(__nv_bfloat162*)(hip)     = h0;
    *(__nv_bfloat162*)(hip + 2) = h1;
    *(__nv_bfloat162*)(lop)     = l0;
    *(__nv_bfloat162*)(lop + 2) = l1;
}

// ---------------------------------------------------------------------------
// Kernel 0: mask preprocessing (dtype-robust: int32 words vs packed bytes)
// ---------------------------------------------------------------------------
__global__ __launch_bounds__(256)
void mask_prep_kernel(const void* __restrict__ mask)
{
    __shared__ int s_packed;
    if (threadIdx.x == 0) s_packed = 0;
    __syncthreads();

    const unsigned* mw = (const unsigned*)mask;
    int bad = 0;
    for (int i = threadIdx.x; i < 2048; i += 256)
        if (mw[i] > 1u) bad = 1;
    if (bad) atomicOr(&s_packed, 1);
    __syncthreads();
    const bool packed = (s_packed != 0);

    const int* mi = (const int*)mask;
    const unsigned char* mb = (const unsigned char*)mask;
    for (int i = threadIdx.x; i < BB * NN; i += 256) {
        const int on = packed ? (int)mb[i] : mi[i];
        g_maskbias[i] = on ? 0.0f : -1e30f;
    }
}

// ---------------------------------------------------------------------------
// Kernel W: split one W[1024x1024] into hi/lo bf16 at slot
// ---------------------------------------------------------------------------
__global__ __launch_bounds__(256)
void wconv_kernel(const float* __restrict__ W, int slot)
{
    const size_t i = ((size_t)blockIdx.x * 256 + threadIdx.x) * 4;
    float4 v = *(const float4*)(W + i);
    const size_t off = (size_t)slot * DD * DD + i;
    hl4_store(v, g_whi + off, g_wlo + off);
}

// ---------------------------------------------------------------------------
// Kernel 1: row LayerNorm over D=1024 -> hi/lo bf16
// ---------------------------------------------------------------------------
__global__ __launch_bounds__(256)
void ln_x_kernel(const float* __restrict__ x,
                 const float* __restrict__ w,
                 const float* __restrict__ b)
{
    __shared__ float red_s[8];
    __shared__ float red_q[8];
    __shared__ float stats[2];
    const int row = blockIdx.x;
    const int t = threadIdx.x;
    const int lane = t & 31, warp = t >> 5;

    const float* xr = x + (long)row * DD;
    float4 xv = *(const float4*)(xr + t * 4);
    float sum = xv.x + xv.y + xv.z + xv.w;
    float ssq = fmaf(xv.x, xv.x, fmaf(xv.y, xv.y, fmaf(xv.z, xv.z, xv.w * xv.w)));
    #pragma unroll
    for (int o = 16; o > 0; o >>= 1) {
        sum += __shfl_xor_sync(0xffffffffu, sum, o);
        ssq += __shfl_xor_sync(0xffffffffu, ssq, o);
    }
    if (lane == 0) { red_s[warp] = sum; red_q[warp] = ssq; }
    __syncthreads();
    if (warp == 0) {
        float a = (lane < 8) ? red_s[lane] : 0.0f;
        float c = (lane < 8) ? red_q[lane] : 0.0f;
        #pragma unroll
        for (int o = 4; o > 0; o >>= 1) {
            a += __shfl_xor_sync(0xffffffffu, a, o);
            c += __shfl_xor_sync(0xffffffffu, c, o);
        }
        if (lane == 0) { stats[0] = a * (1.0f / DD); stats[1] = c * (1.0f / DD); }
    }
    __syncthreads();
    const float mean = stats[0];
    const float var = stats[1] - mean * mean;
    const float rstd = rsqrtf(var + LN_EPS);

    float4 wv = *(const float4*)(w + t * 4);
    float4 bv = *(const float4*)(b + t * 4);
    float4 ov;
    ov.x = (xv.x - mean) * rstd * wv.x + bv.x;
    ov.y = (xv.y - mean) * rstd * wv.y + bv.y;
    ov.z = (xv.z - mean) * rstd * wv.z + bv.z;
    ov.w = (xv.w - mean) * rstd * wv.w + bv.w;
    const size_t off = (size_t)row * DD + t * 4;
    hl4_store(ov, g_xn_hi + off, g_xn_lo + off);
}

// ---------------------------------------------------------------------------
// Kernel 2: HMMA bf16x3 GEMM  C[8192,1024] = A @ W^T (+bias)
// 128x128 CTA tile, K-slab 64, 8 warps (4M x 2N), warp tile 32x64.
// 3 passes: Ahi*Bhi + Ahi*Blo + Alo*Bhi.
// MODE 0: A=g_ao(hi/lo), C=Cout plain.  MODE 1/2/3: A=g_xn, scatter + bias.
// ---------------------------------------------------------------------------
#define SSTR 72                            // smem row stride (bf16 elems), 144B
#define BUF_ELE (128 * SSTR)               // 9216 elems = 18KB
#define GEMM_SMEM (4 * BUF_ELE * 2)        // 73728 B

template<int MODE>
__global__ __launch_bounds__(256)
void gemm_mma(const float* __restrict__ bias, float* __restrict__ Cout)
{
    extern __shared__ __nv_bfloat16 sm[];
    __nv_bfloat16* sAh = sm;
    __nv_bfloat16* sAl = sm + BUF_ELE;
    __nv_bfloat16* sBh = sm + 2 * BUF_ELE;
    __nv_bfloat16* sBl = sm + 3 * BUF_ELE;
    const uint32_t u0 = s2u(sm);

    const int tid = threadIdx.x;
    const int wid = tid >> 5, lane = tid & 31;
    const int wm = (wid & 3) << 5;          // warp M offset (0,32,64,96)
    const int wn = (wid >> 2) << 6;         // warp N offset (0,64)
    const int bm = blockIdx.y << 7;
    const int bn = blockIdx.x << 7;

    const __nv_bfloat16* gAh = (MODE == 0) ? g_ao_hi : g_xn_hi;
    const __nv_bfloat16* gAl = (MODE == 0) ? g_ao_lo : g_xn_lo;
    const int wslot = (MODE == 0) ? 3 : (MODE - 1);
    const __nv_bfloat16* gBh = g_whi + (size_t)wslot * DD * DD;
    const __nv_bfloat16* gBl = g_wlo + (size_t)wslot * DD * DD;
    float* C = (MODE == 1) ? g_q : (MODE == 2) ? g_k : (MODE == 3) ? g_v : Cout;

    float acc[2][8][4];
    #pragma unroll
    for (int i = 0; i < 2; i++)
        #pragma unroll
        for (int j = 0; j < 8; j++)
            #pragma unroll
            for (int k = 0; k < 4; k++) acc[i][j][k] = 0.0f;

    // per-lane ldmatrix address offsets (bytes)
    const int aRow = (lane & 7) + ((lane & 8) ? 8 : 0);
    const int aK   = (lane & 16) ? 8 : 0;
    const int bRow = (lane & 7) + ((lane & 16) ? 8 : 0);
    const int bK   = (lane & 8) ? 8 : 0;
    const uint32_t aAh = u0 + ((wm + aRow) * SSTR + aK) * 2;
    const uint32_t aAl = aAh + BUF_ELE * 2;
    const uint32_t aBh = u0 + 2 * BUF_ELE * 2 + ((wn + bRow) * SSTR + bK) * 2;
    const uint32_t aBl = aBh + BUF_ELE * 2;

    const int ldRow = tid >> 3;             // 0..31
    const int ldCol = (tid & 7) << 3;       // 0..56 step 8

    for (int kt = 0; kt < DD; kt += 64) {
        #pragma unroll
        for (int i = 0; i < 4; i++) {
            const int row = ldRow + (i << 5);
            const int so = row * SSTR + ldCol;
            const size_t ga = (size_t)(bm + row) * DD + kt + ldCol;
            const size_t gb = (size_t)(bn + row) * DD + kt + ldCol;
            *(uint4*)(sAh + so) = *(const uint4*)(gAh + ga);
            *(uint4*)(sAl + so) = *(const uint4*)(gAl + ga);
            *(uint4*)(sBh + so) = *(const uint4*)(gBh + gb);
            *(uint4*)(sBl + so) = *(const uint4*)(gBl + gb);
        }
        __syncthreads();

        #pragma unroll
        for (int k16 = 0; k16 < 4; k16++) {
            const uint32_t koff = (k16 << 4) * 2;   // kb*2 bytes
            uint32_t ah[2][4], al[2][4];
            #pragma unroll
            for (int mt = 0; mt < 2; mt++) {
                const uint32_t moff = (mt << 4) * SSTR * 2;
                ldsm4(ah[mt][0], ah[mt][1], ah[mt][2], ah[mt][3], aAh + moff + koff);
                ldsm4(al[mt][0], al[mt][1], al[mt][2], al[mt][3], aAl + moff + koff);
            }
            #pragma unroll
            for (int p = 0; p < 4; p++) {           // pairs of n8 tiles
                const uint32_t noff = (p << 4) * SSTR * 2;
                uint32_t bh0, bh1, bh2, bh3, bl0, bl1, bl2, bl3;
                ldsm4(bh0, bh1, bh2, bh3, aBh + noff + koff);
                ldsm4(bl0, bl1, bl2, bl3, aBl + noff + koff);
                #pragma unroll
                for (int mt = 0; mt < 2; mt++) {
                    mma16816(acc[mt][2 * p + 0], ah[mt], bh0, bh1);
                    mma16816(acc[mt][2 * p + 1], ah[mt], bh2, bh3);
                    mma16816(acc[mt][2 * p + 0], ah[mt], bl0, bl1);
                    mma16816(acc[mt][2 * p + 1], ah[mt], bl2, bl3);
                    mma16816(acc[mt][2 * p + 0], al[mt], bh0, bh1);
                    mma16816(acc[mt][2 * p + 1], al[mt], bh2, bh3);
                }
            }
        }
        __syncthreads();
    }

    // Epilogue
    const int g = lane >> 2, tq = lane & 3;
    #pragma unroll
    for (int mt = 0; mt < 2; mt++) {
        #pragma unroll
        for (int nt = 0; nt < 8; nt++) {
            const int c = bn + wn + nt * 8 + 2 * tq;
            #pragma unroll
            for (int half = 0; half < 2; half++) {
                const int r = bm + wm + mt * 16 + g + half * 8;
                float2 v;
                v.x = acc[mt][nt][2 * half + 0];
                v.y = acc[mt][nt][2 * half + 1];
                if (MODE == 0) {
                    *(float2*)(Cout + (size_t)r * DD + c) = v;
                } else {
                    const float2 bv = *(const float2*)(bias + c);
                    v.x += bv.x; v.y += bv.y;
                    const int h = c >> 6;
                    float* dst = C + ((((size_t)((r >> 11) * HH + h)) * NN
                                      + (r & 2047)) << 6) + (c & 63);
                    *(float2*)dst = v;
                }
            }
        }
    }
}

// ---------------------------------------------------------------------------
// Kernel 3: per-head LayerNorm over DH=64 (in-place on g_q / g_k)
// ---------------------------------------------------------------------------
template<int WHICH>   // 1 = q (apply scale), 2 = k
__global__ __launch_bounds__(256)
void headln_kernel(const float* __restrict__ w,
                   const float* __restrict__ b,
                   float sc)
{
    float* base = (WHICH == 1) ? g_q : g_k;
    const int warp = threadIdx.x >> 5;
    const int lane = threadIdx.x & 31;
    const long row = (long)blockIdx.x * 8 + warp;
    float* p = base + row * DH;

    float2 xv = *(float2*)(p + lane * 2);
    float sum = xv.x + xv.y;
    float ssq = fmaf(xv.x, xv.x, xv.y * xv.y);
    #pragma unroll
    for (int o = 16; o > 0; o >>= 1) {
        sum += __shfl_xor_sync(0xffffffffu, sum, o);
        ssq += __shfl_xor_sync(0xffffffffu, ssq, o);
    }
    const float mean = sum * (1.0f / DH);
    const float var = ssq * (1.0f / DH) - mean * mean;
    const float rstd = rsqrtf(var + LN_EPS);

    float2 wv = *(const float2*)(w + lane * 2);
    float2 bv = *(const float2*)(b + lane * 2);
    float2 ov;
    ov.x = ((xv.x - mean) * rstd * wv.x + bv.x) * sc;
    ov.y = ((xv.y - mean) * rstd * wv.y + bv.y) * sc;
    *(float2*)(p + lane * 2) = ov;
}

// ---------------------------------------------------------------------------
// Kernel 4: flash attention, fp32 -> hi/lo bf16 output
// ---------------------------------------------------------------------------
__global__ __launch_bounds__(128)
void attn_kernel()
{
    __shared__ __align__(16) float Ks[64 * 64];
    __shared__ __align__(16) float Vs[64 * 64];
    __shared__ float mb[64];

    const int t = threadIdx.x;
    const int b = blockIdx.z;
    const int h = blockIdx.y;
    const int n = blockIdx.x * 128 + t;

    const long head_off = ((long)(b * HH + h)) * NN;
    const float* qp = g_q + ((head_off + n) << 6);
    float qr[64];
    #pragma unroll
    for (int i = 0; i < 16; i++) {
        float4 tmp = *(const float4*)(qp + i * 4);
        qr[i * 4 + 0] = tmp.x; qr[i * 4 + 1] = tmp.y;
        qr[i * 4 + 2] = tmp.z; qr[i * 4 + 3] = tmp.w;
    }

    float acc[64];
    #pragma unroll
    for (int d = 0; d < 64; d++) acc[d] = 0.0f;
    float m = -1e30f, l = 0.0f;

    const float* kbase = g_k + (head_off << 6);
    const float* vbase = g_v + (head_off << 6);
    const float* mrow = g_maskbias + b * NN;

    for (int kt = 0; kt < NN; kt += 64) {
        const float* ksrc = kbase + ((long)kt << 6);
        const float* vsrc = vbase + ((long)kt << 6);
        #pragma unroll
        for (int i = 0; i < 8; i++) {
            const int f = t + i * 128;
            *(float4*)&Ks[f * 4] = *(const float4*)(ksrc + f * 4);
            *(float4*)&Vs[f * 4] = *(const float4*)(vsrc + f * 4);
        }
        if (t < 64) mb[t] = mrow[kt + t];
        __syncthreads();

        #pragma unroll 1
        for (int c = 0; c < 64; c += 8) {
            float s[8];
            #pragma unroll
            for (int j = 0; j < 8; j++) {
                const float* kj = &Ks[(c + j) * 64];
                float s0 = 0.0f, s1 = 0.0f, s2 = 0.0f, s3 = 0.0f;
                #pragma unroll
                for (int d = 0; d < 64; d += 4) {
                    float4 kv = *(const float4*)(kj + d);
                    s0 = fmaf(qr[d + 0], kv.x, s0);
                    s1 = fmaf(qr[d + 1], kv.y, s1);
                    s2 = fmaf(qr[d + 2], kv.z, s2);
                    s3 = fmaf(qr[d + 3], kv.w, s3);
                }
                s[j] = (s0 + s1) + (s2 + s3) + mb[c + j];
            }
            float cm = s[0];
            #pragma unroll
            for (int j = 1; j < 8; j++) cm = fmaxf(cm, s[j]);
            const float mnew = fmaxf(m, cm);
            const float scale = __expf(m - mnew);
            l *= scale;
            #pragma unroll
            for (int d = 0; d < 64; d++) acc[d] *= scale;
            #pragma unroll
            for (int j = 0; j < 8; j++) {
                const float p = __expf(s[j] - mnew);
                l += p;
                const float* vj = &Vs[(c + j) * 64];
                #pragma unroll
                for (int d = 0; d < 64; d += 4) {
                    float4 vv = *(const float4*)(vj + d);
                    acc[d + 0] = fmaf(p, vv.x, acc[d + 0]);
                    acc[d + 1] = fmaf(p, vv.y, acc[d + 1]);
                    acc[d + 2] = fmaf(p, vv.z, acc[d + 2]);
                    acc[d + 3] = fmaf(p, vv.w, acc[d + 3]);
                }
            }
            m = mnew;
        }
        __syncthreads();
    }

    const float inv = 1.0f / l;
    const size_t ob = ((size_t)(b * NN + n)) * DD + (h << 6);
    #pragma unroll
    for (int d = 0; d < 64; d += 4) {
        float4 o;
        o.x = acc[d + 0] * inv; o.y = acc[d + 1] * inv;
        o.z = acc[d + 2] * inv; o.w = acc[d + 3] * inv;
        hl4_store(o, g_ao_hi + ob + d, g_ao_lo + ob + d);
    }
}

// ---------------------------------------------------------------------------
// Launch
// ---------------------------------------------------------------------------
extern "C" void kernel_launch(void* const* d_in, const int* in_sizes, int n_in,
                              void* d_out, int out_size)
{
    const float* x       = (const float*)d_in[0];
    const void*  mask    = (const void*)d_in[1];
    const float* norm_w  = (const float*)d_in[2];
    const float* norm_b  = (const float*)d_in[3];
    const float* qn_w    = (const float*)d_in[4];
    const float* qn_b    = (const float*)d_in[5];
    const float* kn_w    = (const float*)d_in[6];
    const float* kn_b    = (const float*)d_in[7];
    const float* Wq      = (const float*)d_in[8];
    const float* bq      = (const float*)d_in[9];
    const float* Wk      = (const float*)d_in[10];
    const float* bk      = (const float*)d_in[11];
    const float* Wv      = (const float*)d_in[12];
    const float* bv      = (const float*)d_in[13];
    const float* Wo      = (const float*)d_in[14];
    float* out = (float*)d_out;

    static bool attr_done = false;
    if (!attr_done) {
        cudaFuncSetAttribute(gemm_mma<0>, cudaFuncAttributeMaxDynamicSharedMemorySize, GEMM_SMEM);
        cudaFuncSetAttribute(gemm_mma<1>, cudaFuncAttributeMaxDynamicSharedMemorySize, GEMM_SMEM);
        cudaFuncSetAttribute(gemm_mma<2>, cudaFuncAttributeMaxDynamicSharedMemorySize, GEMM_SMEM);
        cudaFuncSetAttribute(gemm_mma<3>, cudaFuncAttributeMaxDynamicSharedMemorySize, GEMM_SMEM);
        attr_done = true;
    }

    // 0. Mask -> float bias; W -> hi/lo bf16
    mask_prep_kernel<<<1, 256>>>(mask);
    wconv_kernel<<<1024, 256>>>(Wq, 0);
    wconv_kernel<<<1024, 256>>>(Wk, 1);
    wconv_kernel<<<1024, 256>>>(Wv, 2);
    wconv_kernel<<<1024, 256>>>(Wo, 3);

    // 1. LN(x) -> hi/lo bf16
    ln_x_kernel<<<BN, 256>>>(x, norm_w, norm_b);

    // 2. QKV projections (HMMA bf16x3) -> g_q/g_k/g_v [b,h,n,dh]
    dim3 gg(DD / 128, BN / 128);   // (8, 64)
    gemm_mma<1><<<gg, 256, GEMM_SMEM>>>(bq, nullptr);
    gemm_mma<2><<<gg, 256, GEMM_SMEM>>>(bk, nullptr);
    gemm_mma<3><<<gg, 256, GEMM_SMEM>>>(bv, nullptr);

    // 3. Per-head LN (q scaled by DH^-0.5)
    const int ln_blocks = (BB * HH * NN) / 8;
    headln_kernel<1><<<ln_blocks, 256>>>(qn_w, qn_b, 0.125f);
    headln_kernel<2><<<ln_blocks, 256>>>(kn_w, kn_b, 1.0f);

    // 4. Flash attention -> g_ao hi/lo
    attn_kernel<<<dim3(NN / 128, HH, BB), 128>>>();

    // 5. Output projection (HMMA bf16x3) -> d_out
    gemm_mma<0><<<gg, 256, GEMM_SMEM>>>(nullptr, out);
}

// round 5
// speedup vs baseline: 2.5608x; 2.0328x over previous
#include <cuda_runtime.h>
#include <cuda_bf16.h>
#include <cstdint>

// Problem constants
#define BB 4
#define NN 2048
#define DD 1024
#define HH 16
#define DH 64
#define BN (BB*NN)          // 8192
#define LN_EPS 1e-5f

// ---------------------------------------------------------------------------
// Device scratch (no allocation allowed)
// ---------------------------------------------------------------------------
__device__ __nv_bfloat16 g_xn_hi[BN * DD];
__device__ __nv_bfloat16 g_xn_lo[BN * DD];
__device__ __nv_bfloat16 g_ao_hi[BN * DD];
__device__ __nv_bfloat16 g_ao_lo[BN * DD];
__device__ __nv_bfloat16 g_whi[4 * DD * DD];
__device__ __nv_bfloat16 g_wlo[4 * DD * DD];
__device__ float g_q[BB * HH * NN * DH];
__device__ float g_k[BB * HH * NN * DH];
__device__ __nv_bfloat16 g_qh[BB * HH * NN * DH];
__device__ __nv_bfloat16 g_ql[BB * HH * NN * DH];
__device__ __nv_bfloat16 g_kh[BB * HH * NN * DH];
__device__ __nv_bfloat16 g_kl[BB * HH * NN * DH];
__device__ __nv_bfloat16 g_vh[BB * HH * NN * DH];
__device__ __nv_bfloat16 g_vl[BB * HH * NN * DH];
__device__ float g_maskbias[BB * NN];

// ---------------------------------------------------------------------------
// Helpers
// ---------------------------------------------------------------------------
__device__ __forceinline__ uint32_t s2u(const void* p) {
    uint32_t a;
    asm("{ .reg .u64 t; cvta.to.shared.u64 t, %1; cvt.u32.u64 %0, t; }"
        : "=r"(a) : "l"(p));
    return a;
}

__device__ __forceinline__ void ldsm4(uint32_t& r0, uint32_t& r1,
                                      uint32_t& r2, uint32_t& r3,
                                      uint32_t addr) {
    asm volatile("ldmatrix.sync.aligned.m8n8.x4.shared.b16 {%0,%1,%2,%3}, [%4];"
                 : "=r"(r0), "=r"(r1), "=r"(r2), "=r"(r3) : "r"(addr));
}

__device__ __forceinline__ void ldsm4t(uint32_t& r0, uint32_t& r1,
                                       uint32_t& r2, uint32_t& r3,
                                       uint32_t addr) {
    asm volatile("ldmatrix.sync.aligned.m8n8.x4.trans.shared.b16 {%0,%1,%2,%3}, [%4];"
                 : "=r"(r0), "=r"(r1), "=r"(r2), "=r"(r3) : "r"(addr));
}

__device__ __forceinline__ void mma16816(float* c, const uint32_t* a,
                                         uint32_t b0, uint32_t b1) {
    asm volatile(
        "mma.sync.aligned.m16n8k16.row.col.f32.bf16.bf16.f32 "
        "{%0,%1,%2,%3}, {%4,%5,%6,%7}, {%8,%9}, {%0,%1,%2,%3};"
        : "+f"(c[0]), "+f"(c[1]), "+f"(c[2]), "+f"(c[3])
        : "r"(a[0]), "r"(a[1]), "r"(a[2]), "r"(a[3]), "r"(b0), "r"(b1));
}

// hi/lo bf16 split of a float pair -> two packed bf16x2 regs
__device__ __forceinline__ void hl_pack(float a, float b, uint32_t& hi, uint32_t& lo) {
    __nv_bfloat162 h = __float22bfloat162_rn(make_float2(a, b));
    float2 f = __bfloat1622float2(h);
    __nv_bfloat162 l = __float22bfloat162_rn(make_float2(a - f.x, b - f.y));
    hi = *reinterpret_cast<uint32_t*>(&h);
    lo = *reinterpret_cast<uint32_t*>(&l);
}

__device__ __forceinline__ void hl2_store(float a, float b,
                                          __nv_bfloat16* hip, __nv_bfloat16* lop) {
    uint32_t hi, lo;
    hl_pack(a, b, hi, lo);
    *(uint32_t*)hip = hi;
    *(uint32_t*)lop = lo;
}

__device__ __forceinline__ void hl4_store(float4 v, __nv_bfloat16* hip,
                                          __nv_bfloat16* lop) {
    hl2_store(v.x, v.y, hip, lop);
    hl2_store(v.z, v.w, hip + 2, lop + 2);
}

// ---------------------------------------------------------------------------
// Kernel 0: mask preprocessing (dtype-robust: int32 words vs packed bytes)
// ---------------------------------------------------------------------------
__global__ __launch_bounds__(256)
void mask_prep_kernel(const void* __restrict__ mask)
{
    __shared__ int s_packed;
    if (threadIdx.x == 0) s_packed = 0;
    __syncthreads();

    const unsigned* mw = (const unsigned*)mask;
    int bad = 0;
    for (int i = threadIdx.x; i < 2048; i += 256)
        if (mw[i] > 1u) bad = 1;
    if (bad) atomicOr(&s_packed, 1);
    __syncthreads();
    const bool packed = (s_packed != 0);

    const int* mi = (const int*)mask;
    const unsigned char* mb = (const unsigned char*)mask;
    for (int i = threadIdx.x; i < BB * NN; i += 256) {
        const int on = packed ? (int)mb[i] : mi[i];
        g_maskbias[i] = on ? 0.0f : -1e30f;
    }
}

// ---------------------------------------------------------------------------
// Kernel W: split one W[1024x1024] into hi/lo bf16 at slot
// ---------------------------------------------------------------------------
__global__ __launch_bounds__(256)
void wconv_kernel(const float* __restrict__ W, int slot)
{
    const size_t i = ((size_t)blockIdx.x * 256 + threadIdx.x) * 4;
    float4 v = *(const float4*)(W + i);
    const size_t off = (size_t)slot * DD * DD + i;
    hl4_store(v, g_whi + off, g_wlo + off);
}

// ---------------------------------------------------------------------------
// Kernel 1: row LayerNorm over D=1024 -> hi/lo bf16
// ---------------------------------------------------------------------------
__global__ __launch_bounds__(256)
void ln_x_kernel(const float* __restrict__ x,
                 const float* __restrict__ w,
                 const float* __restrict__ b)
{
    __shared__ float red_s[8];
    __shared__ float red_q[8];
    __shared__ float stats[2];
    const int row = blockIdx.x;
    const int t = threadIdx.x;
    const int lane = t & 31, warp = t >> 5;

    const float* xr = x + (long)row * DD;
    float4 xv = *(const float4*)(xr + t * 4);
    float sum = xv.x + xv.y + xv.z + xv.w;
    float ssq = fmaf(xv.x, xv.x, fmaf(xv.y, xv.y, fmaf(xv.z, xv.z, xv.w * xv.w)));
    #pragma unroll
    for (int o = 16; o > 0; o >>= 1) {
        sum += __shfl_xor_sync(0xffffffffu, sum, o);
        ssq += __shfl_xor_sync(0xffffffffu, ssq, o);
    }
    if (lane == 0) { red_s[warp] = sum; red_q[warp] = ssq; }
    __syncthreads();
    if (warp == 0) {
        float a = (lane < 8) ? red_s[lane] : 0.0f;
        float c = (lane < 8) ? red_q[lane] : 0.0f;
        #pragma unroll
        for (int o = 4; o > 0; o >>= 1) {
            a += __shfl_xor_sync(0xffffffffu, a, o);
            c += __shfl_xor_sync(0xffffffffu, c, o);
        }
        if (lane == 0) { stats[0] = a * (1.0f / DD); stats[1] = c * (1.0f / DD); }
    }
    __syncthreads();
    const float mean = stats[0];
    const float var = stats[1] - mean * mean;
    const float rstd = rsqrtf(var + LN_EPS);

    float4 wv = *(const float4*)(w + t * 4);
    float4 bv = *(const float4*)(b + t * 4);
    float4 ov;
    ov.x = (xv.x - mean) * rstd * wv.x + bv.x;
    ov.y = (xv.y - mean) * rstd * wv.y + bv.y;
    ov.z = (xv.z - mean) * rstd * wv.z + bv.z;
    ov.w = (xv.w - mean) * rstd * wv.w + bv.w;
    const size_t off = (size_t)row * DD + t * 4;
    hl4_store(ov, g_xn_hi + off, g_xn_lo + off);
}

// ---------------------------------------------------------------------------
// Kernel 2: HMMA bf16x3 GEMM  C[8192,1024] = A @ W^T (+bias)
// 128x128 CTA tile, K-slab 64, 8 warps (4M x 2N), warp tile 32x64.
// MODE 0: A=g_ao(hi/lo), C=Cout plain.  MODE 1/2: scatter fp32 + bias.
// MODE 3: scatter hi/lo bf16 (V) + bias.
// ---------------------------------------------------------------------------
#define SSTR 72                            // smem row stride (bf16 elems), 144B
#define BUF_ELE (128 * SSTR)               // 9216 elems = 18KB
#define GEMM_SMEM (4 * BUF_ELE * 2)        // 73728 B

template<int MODE>
__global__ __launch_bounds__(256)
void gemm_mma(const float* __restrict__ bias, float* __restrict__ Cout)
{
    extern __shared__ __nv_bfloat16 smg[];
    __nv_bfloat16* sAh = smg;
    __nv_bfloat16* sAl = smg + BUF_ELE;
    __nv_bfloat16* sBh = smg + 2 * BUF_ELE;
    __nv_bfloat16* sBl = smg + 3 * BUF_ELE;
    const uint32_t u0 = s2u(smg);

    const int tid = threadIdx.x;
    const int wid = tid >> 5, lane = tid & 31;
    const int wm = (wid & 3) << 5;          // warp M offset (0,32,64,96)
    const int wn = (wid >> 2) << 6;         // warp N offset (0,64)
    const int bm = blockIdx.y << 7;
    const int bn = blockIdx.x << 7;

    const __nv_bfloat16* gAh = (MODE == 0) ? g_ao_hi : g_xn_hi;
    const __nv_bfloat16* gAl = (MODE == 0) ? g_ao_lo : g_xn_lo;
    const int wslot = (MODE == 0) ? 3 : (MODE - 1);
    const __nv_bfloat16* gBh = g_whi + (size_t)wslot * DD * DD;
    const __nv_bfloat16* gBl = g_wlo + (size_t)wslot * DD * DD;
    float* C = (MODE == 1) ? g_q : (MODE == 2) ? g_k : Cout;

    float acc[2][8][4];
    #pragma unroll
    for (int i = 0; i < 2; i++)
        #pragma unroll
        for (int j = 0; j < 8; j++)
            #pragma unroll
            for (int k = 0; k < 4; k++) acc[i][j][k] = 0.0f;

    // per-lane ldmatrix address offsets (bytes)
    const int aRow = (lane & 7) + ((lane & 8) ? 8 : 0);
    const int aK   = (lane & 16) ? 8 : 0;
    const int bRow = (lane & 7) + ((lane & 16) ? 8 : 0);
    const int bK   = (lane & 8) ? 8 : 0;
    const uint32_t aAh = u0 + ((wm + aRow) * SSTR + aK) * 2;
    const uint32_t aAl = aAh + BUF_ELE * 2;
    const uint32_t aBh = u0 + 2 * BUF_ELE * 2 + ((wn + bRow) * SSTR + bK) * 2;
    const uint32_t aBl = aBh + BUF_ELE * 2;

    const int ldRow = tid >> 3;             // 0..31
    const int ldCol = (tid & 7) << 3;       // 0..56 step 8

    for (int kt = 0; kt < DD; kt += 64) {
        #pragma unroll
        for (int i = 0; i < 4; i++) {
            const int row = ldRow + (i << 5);
            const int so = row * SSTR + ldCol;
            const size_t ga = (size_t)(bm + row) * DD + kt + ldCol;
            const size_t gb = (size_t)(bn + row) * DD + kt + ldCol;
            *(uint4*)(sAh + so) = *(const uint4*)(gAh + ga);
            *(uint4*)(sAl + so) = *(const uint4*)(gAl + ga);
            *(uint4*)(sBh + so) = *(const uint4*)(gBh + gb);
            *(uint4*)(sBl + so) = *(const uint4*)(gBl + gb);
        }
        __syncthreads();

        #pragma unroll
        for (int k16 = 0; k16 < 4; k16++) {
            const uint32_t koff = (k16 << 4) * 2;
            uint32_t ah[2][4], al[2][4];
            #pragma unroll
            for (int mt = 0; mt < 2; mt++) {
                const uint32_t moff = (mt << 4) * SSTR * 2;
                ldsm4(ah[mt][0], ah[mt][1], ah[mt][2], ah[mt][3], aAh + moff + koff);
                ldsm4(al[mt][0], al[mt][1], al[mt][2], al[mt][3], aAl + moff + koff);
            }
            #pragma unroll
            for (int p = 0; p < 4; p++) {
                const uint32_t noff = (p << 4) * SSTR * 2;
                uint32_t bh0, bh1, bh2, bh3, bl0, bl1, bl2, bl3;
                ldsm4(bh0, bh1, bh2, bh3, aBh + noff + koff);
                ldsm4(bl0, bl1, bl2, bl3, aBl + noff + koff);
                #pragma unroll
                for (int mt = 0; mt < 2; mt++) {
                    mma16816(acc[mt][2 * p + 0], ah[mt], bh0, bh1);
                    mma16816(acc[mt][2 * p + 1], ah[mt], bh2, bh3);
                    mma16816(acc[mt][2 * p + 0], ah[mt], bl0, bl1);
                    mma16816(acc[mt][2 * p + 1], ah[mt], bl2, bl3);
                    mma16816(acc[mt][2 * p + 0], al[mt], bh0, bh1);
                    mma16816(acc[mt][2 * p + 1], al[mt], bh2, bh3);
                }
            }
        }
        __syncthreads();
    }

    // Epilogue
    const int g = lane >> 2, tq = lane & 3;
    #pragma unroll
    for (int mt = 0; mt < 2; mt++) {
        #pragma unroll
        for (int nt = 0; nt < 8; nt++) {
            const int c = bn + wn + nt * 8 + 2 * tq;
            #pragma unroll
            for (int half = 0; half < 2; half++) {
                const int r = bm + wm + mt * 16 + g + half * 8;
                float2 v;
                v.x = acc[mt][nt][2 * half + 0];
                v.y = acc[mt][nt][2 * half + 1];
                if (MODE == 0) {
                    *(float2*)(Cout + (size_t)r * DD + c) = v;
                } else {
                    const float2 bv = *(const float2*)(bias + c);
                    v.x += bv.x; v.y += bv.y;
                    const int h = c >> 6;
                    const size_t idx = ((((size_t)((r >> 11) * HH + h)) * NN
                                        + (r & 2047)) << 6) + (c & 63);
                    if (MODE == 3) {
                        hl2_store(v.x, v.y, g_vh + idx, g_vl + idx);
                    } else {
                        *(float2*)(C + idx) = v;
                    }
                }
            }
        }
    }
}

// ---------------------------------------------------------------------------
// Kernel 3: per-head LayerNorm over DH=64 -> hi/lo bf16
// ---------------------------------------------------------------------------
template<int WHICH>   // 1 = q (apply scale), 2 = k
__global__ __launch_bounds__(256)
void headln_kernel(const float* __restrict__ w,
                   const float* __restrict__ b,
                   float sc)
{
    const float* base = (WHICH == 1) ? g_q : g_k;
    __nv_bfloat16* oh = (WHICH == 1) ? g_qh : g_kh;
    __nv_bfloat16* ol = (WHICH == 1) ? g_ql : g_kl;
    const int warp = threadIdx.x >> 5;
    const int lane = threadIdx.x & 31;
    const long row = (long)blockIdx.x * 8 + warp;
    const float* p = base + row * DH;

    float2 xv = *(const float2*)(p + lane * 2);
    float sum = xv.x + xv.y;
    float ssq = fmaf(xv.x, xv.x, xv.y * xv.y);
    #pragma unroll
    for (int o = 16; o > 0; o >>= 1) {
        sum += __shfl_xor_sync(0xffffffffu, sum, o);
        ssq += __shfl_xor_sync(0xffffffffu, ssq, o);
    }
    const float mean = sum * (1.0f / DH);
    const float var = ssq * (1.0f / DH) - mean * mean;
    const float rstd = rsqrtf(var + LN_EPS);

    float2 wv = *(const float2*)(w + lane * 2);
    float2 bv = *(const float2*)(b + lane * 2);
    float a = ((xv.x - mean) * rstd * wv.x + bv.x) * sc;
    float c = ((xv.y - mean) * rstd * wv.y + bv.y) * sc;
    hl2_store(a, c, oh + row * DH + lane * 2, ol + row * DH + lane * 2);
}

// ---------------------------------------------------------------------------
// Kernel 4: tensor-core flash attention (HMMA bf16x3 for QK^T and PV)
// grid (16, 16, 4): 128 queries x one (b,h) per CTA; 8 warps x 16 q-rows.
// ---------------------------------------------------------------------------
#define ASTR 72

__global__ __launch_bounds__(256)
void attn_mma_kernel()
{
    __shared__ __align__(16) __nv_bfloat16 sm[4 * 64 * ASTR];  // 36864 B
    __shared__ float mb[64];

    const int tid = threadIdx.x, wid = tid >> 5, lane = tid & 31;
    const int bq = blockIdx.x << 7;
    const int h = blockIdx.y, b = blockIdx.z;
    const size_t head_off = ((size_t)(b * HH + h)) * NN;

    const uint32_t u0 = s2u(sm);
    const uint32_t Kh = u0;
    const uint32_t Kl = u0 + 64 * ASTR * 2;
    const uint32_t Vh = u0 + 2 * 64 * ASTR * 2;
    const uint32_t Vl = u0 + 3 * 64 * ASTR * 2;

    // ldmatrix lane addressing
    const int aRow = (lane & 7) + ((lane & 8) ? 8 : 0);
    const int aK   = (lane & 16) ? 8 : 0;
    const int bRow = (lane & 7) + ((lane & 16) ? 8 : 0);
    const int bK   = (lane & 8) ? 8 : 0;
    const int vRow = (lane & 7) + ((lane & 8) ? 8 : 0);
    const int vCol = (lane & 16) ? 8 : 0;

    // ---- Phase 1: stage Q (128x64 hi/lo) through smem, ldmatrix to regs
    {
        const int r = tid >> 1;
        const int c = (tid & 1) << 5;
        const __nv_bfloat16* sh = g_qh + (head_off + bq + r) * DH + c;
        const __nv_bfloat16* sl = g_ql + (head_off + bq + r) * DH + c;
        #pragma unroll
        for (int i = 0; i < 4; i++) {
            *(uint4*)(sm + r * ASTR + c + i * 8) = *(const uint4*)(sh + i * 8);
            *(uint4*)(sm + 2 * 64 * ASTR + r * ASTR + c + i * 8) = *(const uint4*)(sl + i * 8);
        }
    }
    __syncthreads();

    uint32_t qh[4][4], ql[4][4];
    {
        const uint32_t qb = u0 + ((wid * 16 + aRow) * ASTR + aK) * 2;
        #pragma unroll
        for (int k = 0; k < 4; k++) {
            ldsm4(qh[k][0], qh[k][1], qh[k][2], qh[k][3], qb + (k * 16) * 2);
            ldsm4(ql[k][0], ql[k][1], ql[k][2], ql[k][3],
                  qb + (2 * 64 * ASTR + k * 16) * 2);
        }
    }

    float o[8][4];
    #pragma unroll
    for (int i = 0; i < 8; i++)
        #pragma unroll
        for (int j = 0; j < 4; j++) o[i][j] = 0.0f;
    float m0 = -1e30f, m1 = -1e30f, l0 = 0.0f, l1 = 0.0f;

    const float* mrow = g_maskbias + b * NN;
    const int tq2 = (lane & 3) * 2;

    for (int kt = 0; kt < NN; kt += 64) {
        __syncthreads();
        // load K/V tiles (bf16 hi/lo, pre-split)
        {
            const int r = tid >> 2;
            const int c = (tid & 3) << 4;
            const size_t gidx = (head_off + kt + r) * DH + c;
            const int so = r * ASTR + c;
            #pragma unroll
            for (int i = 0; i < 2; i++) {
                *(uint4*)(sm + so + i * 8)                    = *(const uint4*)(g_kh + gidx + i * 8);
                *(uint4*)(sm + 64 * ASTR + so + i * 8)        = *(const uint4*)(g_kl + gidx + i * 8);
                *(uint4*)(sm + 2 * 64 * ASTR + so + i * 8)    = *(const uint4*)(g_vh + gidx + i * 8);
                *(uint4*)(sm + 3 * 64 * ASTR + so + i * 8)    = *(const uint4*)(g_vl + gidx + i * 8);
            }
            if (tid < 64) mb[tid] = mrow[kt + tid];
        }
        __syncthreads();

        // S = Q K^T  (bf16x3)
        float s[8][4];
        #pragma unroll
        for (int i = 0; i < 8; i++)
            #pragma unroll
            for (int j = 0; j < 4; j++) s[i][j] = 0.0f;

        #pragma unroll
        for (int k = 0; k < 4; k++) {
            #pragma unroll
            for (int p = 0; p < 4; p++) {
                const uint32_t nb = ((p * 16 + bRow) * ASTR + k * 16 + bK) * 2;
                uint32_t bh0, bh1, bh2, bh3, bl0, bl1, bl2, bl3;
                ldsm4(bh0, bh1, bh2, bh3, Kh + nb);
                ldsm4(bl0, bl1, bl2, bl3, Kl + nb);
                mma16816(s[2 * p + 0], qh[k], bh0, bh1);
                mma16816(s[2 * p + 1], qh[k], bh2, bh3);
                mma16816(s[2 * p + 0], qh[k], bl0, bl1);
                mma16816(s[2 * p + 1], qh[k], bl2, bl3);
                mma16816(s[2 * p + 0], ql[k], bh0, bh1);
                mma16816(s[2 * p + 1], ql[k], bh2, bh3);
            }
        }

        // mask + online softmax
        float mx0 = -1e30f, mx1 = -1e30f;
        #pragma unroll
        for (int nt = 0; nt < 8; nt++) {
            const float b0 = mb[nt * 8 + tq2];
            const float b1 = mb[nt * 8 + tq2 + 1];
            s[nt][0] += b0; s[nt][1] += b1;
            s[nt][2] += b0; s[nt][3] += b1;
            mx0 = fmaxf(mx0, fmaxf(s[nt][0], s[nt][1]));
            mx1 = fmaxf(mx1, fmaxf(s[nt][2], s[nt][3]));
        }
        mx0 = fmaxf(mx0, __shfl_xor_sync(0xffffffffu, mx0, 1));
        mx0 = fmaxf(mx0, __shfl_xor_sync(0xffffffffu, mx0, 2));
        mx1 = fmaxf(mx1, __shfl_xor_sync(0xffffffffu, mx1, 1));
        mx1 = fmaxf(mx1, __shfl_xor_sync(0xffffffffu, mx1, 2));
        const float mn0 = fmaxf(m0, mx0), mn1 = fmaxf(m1, mx1);
        const float sc0 = __expf(m0 - mn0), sc1 = __expf(m1 - mn1);
        m0 = mn0; m1 = mn1;
        float ps0 = 0.0f, ps1 = 0.0f;
        #pragma unroll
        for (int nt = 0; nt < 8; nt++) {
            s[nt][0] = __expf(s[nt][0] - m0);
            s[nt][1] = __expf(s[nt][1] - m0);
            s[nt][2] = __expf(s[nt][2] - m1);
            s[nt][3] = __expf(s[nt][3] - m1);
            ps0 += s[nt][0] + s[nt][1];
            ps1 += s[nt][2] + s[nt][3];
        }
        ps0 += __shfl_xor_sync(0xffffffffu, ps0, 1);
        ps0 += __shfl_xor_sync(0xffffffffu, ps0, 2);
        ps1 += __shfl_xor_sync(0xffffffffu, ps1, 1);
        ps1 += __shfl_xor_sync(0xffffffffu, ps1, 2);
        l0 = l0 * sc0 + ps0;
        l1 = l1 * sc1 + ps1;
        #pragma unroll
        for (int nt = 0; nt < 8; nt++) {
            o[nt][0] *= sc0; o[nt][1] *= sc0;
            o[nt][2] *= sc1; o[nt][3] *= sc1;
        }

        // O += P V   (P hi/lo x V hi/lo, 3 passes)
        #pragma unroll
        for (int jj = 0; jj < 4; jj++) {
            uint32_t ph[4], pl[4];
            hl_pack(s[2 * jj][0],     s[2 * jj][1],     ph[0], pl[0]);
            hl_pack(s[2 * jj][2],     s[2 * jj][3],     ph[1], pl[1]);
            hl_pack(s[2 * jj + 1][0], s[2 * jj + 1][1], ph[2], pl[2]);
            hl_pack(s[2 * jj + 1][2], s[2 * jj + 1][3], ph[3], pl[3]);
            #pragma unroll
            for (int p = 0; p < 4; p++) {
                const uint32_t off = ((jj * 16 + vRow) * ASTR + p * 16 + vCol) * 2;
                uint32_t bh0, bh1, bh2, bh3, bl0, bl1, bl2, bl3;
                ldsm4t(bh0, bh1, bh2, bh3, Vh + off);
                ldsm4t(bl0, bl1, bl2, bl3, Vl + off);
                mma16816(o[2 * p + 0], ph, bh0, bh1);
                mma16816(o[2 * p + 1], ph, bh2, bh3);
                mma16816(o[2 * p + 0], ph, bl0, bl1);
                mma16816(o[2 * p + 1], ph, bl2, bl3);
                mma16816(o[2 * p + 0], pl, bh0, bh1);
                mma16816(o[2 * p + 1], pl, bh2, bh3);
            }
        }
    }

    // epilogue -> g_ao hi/lo   [b, n, h*64+dh]
    const float inv0 = 1.0f / l0, inv1 = 1.0f / l1;
    const int g = lane >> 2;
    const int q0 = bq + wid * 16 + g;
    const size_t ob = ((size_t)(b * NN) + q0) * DD + h * DH;
    #pragma unroll
    for (int nt = 0; nt < 8; nt++) {
        const int dh = nt * 8 + tq2;
        hl2_store(o[nt][0] * inv0, o[nt][1] * inv0, g_ao_hi + ob + dh, g_ao_lo + ob + dh);
        hl2_store(o[nt][2] * inv1, o[nt][3] * inv1,
                  g_ao_hi + ob + 8 * DD + dh, g_ao_lo + ob + 8 * DD + dh);
    }
}

// ---------------------------------------------------------------------------
// Launch
// ---------------------------------------------------------------------------
extern "C" void kernel_launch(void* const* d_in, const int* in_sizes, int n_in,
                              void* d_out, int out_size)
{
    const float* x       = (const float*)d_in[0];
    const void*  mask    = (const void*)d_in[1];
    const float* norm_w  = (const float*)d_in[2];
    const float* norm_b  = (const float*)d_in[3];
    const float* qn_w    = (const float*)d_in[4];
    const float* qn_b    = (const float*)d_in[5];
    const float* kn_w    = (const float*)d_in[6];
    const float* kn_b    = (const float*)d_in[7];
    const float* Wq      = (const float*)d_in[8];
    const float* bq      = (const float*)d_in[9];
    const float* Wk      = (const float*)d_in[10];
    const float* bk      = (const float*)d_in[11];
    const float* Wv      = (const float*)d_in[12];
    const float* bv      = (const float*)d_in[13];
    const float* Wo      = (const float*)d_in[14];
    float* out = (float*)d_out;

    static bool attr_done = false;
    if (!attr_done) {
        cudaFuncSetAttribute(gemm_mma<0>, cudaFuncAttributeMaxDynamicSharedMemorySize, GEMM_SMEM);
        cudaFuncSetAttribute(gemm_mma<1>, cudaFuncAttributeMaxDynamicSharedMemorySize, GEMM_SMEM);
        cudaFuncSetAttribute(gemm_mma<2>, cudaFuncAttributeMaxDynamicSharedMemorySize, GEMM_SMEM);
        cudaFuncSetAttribute(gemm_mma<3>, cudaFuncAttributeMaxDynamicSharedMemorySize, GEMM_SMEM);
        attr_done = true;
    }

    // 0. Mask -> float bias; W -> hi/lo bf16
    mask_prep_kernel<<<1, 256>>>(mask);
    wconv_kernel<<<1024, 256>>>(Wq, 0);
    wconv_kernel<<<1024, 256>>>(Wk, 1);
    wconv_kernel<<<1024, 256>>>(Wv, 2);
    wconv_kernel<<<1024, 256>>>(Wo, 3);

    // 1. LN(x) -> hi/lo bf16
    ln_x_kernel<<<BN, 256>>>(x, norm_w, norm_b);

    // 2. QKV projections (HMMA bf16x3); q,k fp32; v hi/lo bf16
    dim3 gg(DD / 128, BN / 128);   // (8, 64)
    gemm_mma<1><<<gg, 256, GEMM_SMEM>>>(bq, nullptr);
    gemm_mma<2><<<gg, 256, GEMM_SMEM>>>(bk, nullptr);
    gemm_mma<3><<<gg, 256, GEMM_SMEM>>>(bv, nullptr);

    // 3. Per-head LN -> q/k hi/lo bf16 (q scaled by DH^-0.5)
    const int ln_blocks = (BB * HH * NN) / 8;
    headln_kernel<1><<<ln_blocks, 256>>>(qn_w, qn_b, 0.125f);
    headln_kernel<2><<<ln_blocks, 256>>>(kn_w, kn_b, 1.0f);

    // 4. Tensor-core flash attention -> g_ao hi/lo
    attn_mma_kernel<<<dim3(NN / 128, HH, BB), 256>>>();

    // 5. Output projection (HMMA bf16x3) -> d_out
    gemm_mma<0><<<gg, 256, GEMM_SMEM>>>(nullptr, out);
}

// round 6
// speedup vs baseline: 2.7093x; 1.0580x over previous
#include <cuda_runtime.h>
#include <cuda_bf16.h>
#include <cstdint>

// Problem constants
#define BB 4
#define NN 2048
#define DD 1024
#define HH 16
#define DH 64
#define BN (BB*NN)          // 8192
#define LN_EPS 1e-5f

// ---------------------------------------------------------------------------
// Device scratch (no allocation allowed)
// ---------------------------------------------------------------------------
__device__ __nv_bfloat16 g_xn_hi[BN * DD];
__device__ __nv_bfloat16 g_xn_lo[BN * DD];
__device__ __nv_bfloat16 g_ao_hi[BN * DD];
__device__ __nv_bfloat16 g_ao_lo[BN * DD];
__device__ __nv_bfloat16 g_whi[4 * DD * DD];
__device__ __nv_bfloat16 g_wlo[4 * DD * DD];
__device__ float g_q[BB * HH * NN * DH];
__device__ float g_k[BB * HH * NN * DH];
__device__ __nv_bfloat16 g_qh[BB * HH * NN * DH];
__device__ __nv_bfloat16 g_ql[BB * HH * NN * DH];
__device__ __nv_bfloat16 g_kh[BB * HH * NN * DH];
__device__ __nv_bfloat16 g_kl[BB * HH * NN * DH];
__device__ __nv_bfloat16 g_vh[BB * HH * NN * DH];
__device__ __nv_bfloat16 g_vl[BB * HH * NN * DH];
__device__ float g_maskbias[BB * NN];
__device__ float g_bqkv[3 * DD];

// ---------------------------------------------------------------------------
// Helpers
// ---------------------------------------------------------------------------
__device__ __forceinline__ uint32_t s2u(const void* p) {
    uint32_t a;
    asm("{ .reg .u64 t; cvta.to.shared.u64 t, %1; cvt.u32.u64 %0, t; }"
        : "=r"(a) : "l"(p));
    return a;
}

__device__ __forceinline__ void cpa16(uint32_t dst, const void* src) {
    asm volatile("cp.async.cg.shared.global [%0], [%1], 16;"
                 :: "r"(dst), "l"(src) : "memory");
}
#define CP_COMMIT() asm volatile("cp.async.commit_group;" ::: "memory")
#define CP_WAIT(N)  asm volatile("cp.async.wait_group %0;" :: "n"(N) : "memory")

__device__ __forceinline__ void ldsm4(uint32_t& r0, uint32_t& r1,
                                      uint32_t& r2, uint32_t& r3,
                                      uint32_t addr) {
    asm volatile("ldmatrix.sync.aligned.m8n8.x4.shared.b16 {%0,%1,%2,%3}, [%4];"
                 : "=r"(r0), "=r"(r1), "=r"(r2), "=r"(r3) : "r"(addr));
}

__device__ __forceinline__ void ldsm4t(uint32_t& r0, uint32_t& r1,
                                       uint32_t& r2, uint32_t& r3,
                                       uint32_t addr) {
    asm volatile("ldmatrix.sync.aligned.m8n8.x4.trans.shared.b16 {%0,%1,%2,%3}, [%4];"
                 : "=r"(r0), "=r"(r1), "=r"(r2), "=r"(r3) : "r"(addr));
}

__device__ __forceinline__ void mma16816(float* c, const uint32_t* a,
                                         uint32_t b0, uint32_t b1) {
    asm volatile(
        "mma.sync.aligned.m16n8k16.row.col.f32.bf16.bf16.f32 "
        "{%0,%1,%2,%3}, {%4,%5,%6,%7}, {%8,%9}, {%0,%1,%2,%3};"
        : "+f"(c[0]), "+f"(c[1]), "+f"(c[2]), "+f"(c[3])
        : "r"(a[0]), "r"(a[1]), "r"(a[2]), "r"(a[3]), "r"(b0), "r"(b1));
}

// hi/lo bf16 split of a float pair -> two packed bf16x2 regs
__device__ __forceinline__ void hl_pack(float a, float b, uint32_t& hi, uint32_t& lo) {
    __nv_bfloat162 h = __float22bfloat162_rn(make_float2(a, b));
    float2 f = __bfloat1622float2(h);
    __nv_bfloat162 l = __float22bfloat162_rn(make_float2(a - f.x, b - f.y));
    hi = *reinterpret_cast<uint32_t*>(&h);
    lo = *reinterpret_cast<uint32_t*>(&l);
}

__device__ __forceinline__ void hl2_store(float a, float b,
                                          __nv_bfloat16* hip, __nv_bfloat16* lop) {
    uint32_t hi, lo;
    hl_pack(a, b, hi, lo);
    *(uint32_t*)hip = hi;
    *(uint32_t*)lop = lo;
}

__device__ __forceinline__ void hl4_store(float4 v, __nv_bfloat16* hip,
                                          __nv_bfloat16* lop) {
    hl2_store(v.x, v.y, hip, lop);
    hl2_store(v.z, v.w, hip + 2, lop + 2);
}

// ---------------------------------------------------------------------------
// Kernel 0: mask preprocessing + bias concat
// ---------------------------------------------------------------------------
__global__ __launch_bounds__(256)
void prep_kernel(const void* __restrict__ mask,
                 const float* __restrict__ bq,
                 const float* __restrict__ bk,
                 const float* __restrict__ bv)
{
    __shared__ int s_packed;
    if (threadIdx.x == 0) s_packed = 0;
    __syncthreads();

    const unsigned* mw = (const unsigned*)mask;
    int bad = 0;
    for (int i = threadIdx.x; i < 2048; i += 256)
        if (mw[i] > 1u) bad = 1;
    if (bad) atomicOr(&s_packed, 1);
    __syncthreads();
    const bool packed = (s_packed != 0);

    const int* mi = (const int*)mask;
    const unsigned char* mb = (const unsigned char*)mask;
    for (int i = threadIdx.x; i < BB * NN; i += 256) {
        const int on = packed ? (int)mb[i] : mi[i];
        g_maskbias[i] = on ? 0.0f : -1e30f;
    }
    for (int i = threadIdx.x; i < DD; i += 256) {
        g_bqkv[i]          = bq[i];
        g_bqkv[DD + i]     = bk[i];
        g_bqkv[2 * DD + i] = bv[i];
    }
}

// ---------------------------------------------------------------------------
// Kernel W: split one W[1024x1024] into hi/lo bf16 at slot
// ---------------------------------------------------------------------------
__global__ __launch_bounds__(256)
void wconv_kernel(const float* __restrict__ W, int slot)
{
    const size_t i = ((size_t)blockIdx.x * 256 + threadIdx.x) * 4;
    float4 v = *(const float4*)(W + i);
    const size_t off = (size_t)slot * DD * DD + i;
    hl4_store(v, g_whi + off, g_wlo + off);
}

// ---------------------------------------------------------------------------
// Kernel 1: row LayerNorm over D=1024 -> hi/lo bf16
// ---------------------------------------------------------------------------
__global__ __launch_bounds__(256)
void ln_x_kernel(const float* __restrict__ x,
                 const float* __restrict__ w,
                 const float* __restrict__ b)
{
    __shared__ float red_s[8];
    __shared__ float red_q[8];
    __shared__ float stats[2];
    const int row = blockIdx.x;
    const int t = threadIdx.x;
    const int lane = t & 31, warp = t >> 5;

    const float* xr = x + (long)row * DD;
    float4 xv = *(const float4*)(xr + t * 4);
    float sum = xv.x + xv.y + xv.z + xv.w;
    float ssq = fmaf(xv.x, xv.x, fmaf(xv.y, xv.y, fmaf(xv.z, xv.z, xv.w * xv.w)));
    #pragma unroll
    for (int o = 16; o > 0; o >>= 1) {
        sum += __shfl_xor_sync(0xffffffffu, sum, o);
        ssq += __shfl_xor_sync(0xffffffffu, ssq, o);
    }
    if (lane == 0) { red_s[warp] = sum; red_q[warp] = ssq; }
    __syncthreads();
    if (warp == 0) {
        float a = (lane < 8) ? red_s[lane] : 0.0f;
        float c = (lane < 8) ? red_q[lane] : 0.0f;
        #pragma unroll
        for (int o = 4; o > 0; o >>= 1) {
            a += __shfl_xor_sync(0xffffffffu, a, o);
            c += __shfl_xor_sync(0xffffffffu, c, o);
        }
        if (lane == 0) { stats[0] = a * (1.0f / DD); stats[1] = c * (1.0f / DD); }
    }
    __syncthreads();
    const float mean = stats[0];
    const float var = stats[1] - mean * mean;
    const float rstd = rsqrtf(var + LN_EPS);

    float4 wv = *(const float4*)(w + t * 4);
    float4 bv = *(const float4*)(b + t * 4);
    float4 ov;
    ov.x = (xv.x - mean) * rstd * wv.x + bv.x;
    ov.y = (xv.y - mean) * rstd * wv.y + bv.y;
    ov.z = (xv.z - mean) * rstd * wv.z + bv.z;
    ov.w = (xv.w - mean) * rstd * wv.w + bv.w;
    const size_t off = (size_t)row * DD + t * 4;
    hl4_store(ov, g_xn_hi + off, g_xn_lo + off);
}

// ---------------------------------------------------------------------------
// Kernel 2: HMMA bf16x3 GEMM, cp.async double-buffered, K-slab 32.
// 128x128 CTA tile, 8 warps (4M x 2N), warp tile 32x64.
// MODE 0: A=g_ao(hi/lo), B=Wo slot3, C=Cout plain (grid 8x64).
// MODE 4: fused QKV, A=g_xn, B=slots 0..2 (N=3072, grid 24x64),
//         scatter: q,k fp32 + bias; v hi/lo bf16 + bias.
// ---------------------------------------------------------------------------
#define KSL 32
#define SST2 40                              // 32 + 8 pad (80B rows)
#define BUF2 (128 * SST2)                    // 5120 elems
#define STAGE_ELE (4 * BUF2)                 // 20480 elems = 40960 B
#define GEMM_SMEM2 (2 * STAGE_ELE * 2)       // 81920 B

template<int MODE>
__global__ __launch_bounds__(256, 2)
void gemm_mma2(float* __restrict__ Cout)
{
    extern __shared__ __nv_bfloat16 smg[];
    const uint32_t u0 = s2u(smg);

    const int tid = threadIdx.x;
    const int wid = tid >> 5, lane = tid & 31;
    const int wm = (wid & 3) << 5;
    const int wn = (wid >> 2) << 6;
    const int bm = blockIdx.y << 7;
    const int bn = blockIdx.x << 7;

    const __nv_bfloat16* gAh = (MODE == 0) ? g_ao_hi : g_xn_hi;
    const __nv_bfloat16* gAl = (MODE == 0) ? g_ao_lo : g_xn_lo;
    const __nv_bfloat16* gBh = (MODE == 0) ? (g_whi + (size_t)3 * DD * DD) : g_whi;
    const __nv_bfloat16* gBl = (MODE == 0) ? (g_wlo + (size_t)3 * DD * DD) : g_wlo;

    float acc[2][8][4];
    #pragma unroll
    for (int i = 0; i < 2; i++)
        #pragma unroll
        for (int j = 0; j < 8; j++)
            #pragma unroll
            for (int k = 0; k < 4; k++) acc[i][j][k] = 0.0f;

    // cp.async load mapping: thread -> (row, 16-elem half)
    const int lrow = tid >> 1;
    const int lhalf = (tid & 1) << 4;
    const __nv_bfloat16* pAh = gAh + (size_t)(bm + lrow) * DD + lhalf;
    const __nv_bfloat16* pAl = gAl + (size_t)(bm + lrow) * DD + lhalf;
    const __nv_bfloat16* pBh = gBh + (size_t)(bn + lrow) * DD + lhalf;
    const __nv_bfloat16* pBl = gBl + (size_t)(bn + lrow) * DD + lhalf;
    const uint32_t dbase = u0 + (lrow * SST2 + lhalf) * 2;

    // ldmatrix lane addressing
    const int aRow = (lane & 7) + ((lane & 8) ? 8 : 0);
    const int aK   = (lane & 16) ? 8 : 0;
    const int bRow = (lane & 7) + ((lane & 16) ? 8 : 0);
    const int bK   = (lane & 8) ? 8 : 0;

    #define ISSUE_STAGE(kt, stg) do {                                        \
        const uint32_t d_ = dbase + (stg) * (STAGE_ELE * 2);                  \
        cpa16(d_ + 0 * BUF2 * 2,      pAh + (kt));                            \
        cpa16(d_ + 0 * BUF2 * 2 + 16, pAh + (kt) + 8);                        \
        cpa16(d_ + 1 * BUF2 * 2,      pAl + (kt));                            \
        cpa16(d_ + 1 * BUF2 * 2 + 16, pAl + (kt) + 8);                        \
        cpa16(d_ + 2 * BUF2 * 2,      pBh + (kt));                            \
        cpa16(d_ + 2 * BUF2 * 2 + 16, pBh + (kt) + 8);                        \
        cpa16(d_ + 3 * BUF2 * 2,      pBl + (kt));                            \
        cpa16(d_ + 3 * BUF2 * 2 + 16, pBl + (kt) + 8);                        \
        CP_COMMIT();                                                          \
    } while (0)

    ISSUE_STAGE(0, 0);

    const int NSLAB = DD / KSL;   // 32
    for (int s = 0; s < NSLAB; s++) {
        if (s + 1 < NSLAB) {
            ISSUE_STAGE((s + 1) * KSL, (s + 1) & 1);
            CP_WAIT(1);
        } else {
            CP_WAIT(0);
        }
        __syncthreads();

        const uint32_t sb = u0 + (s & 1) * (STAGE_ELE * 2);
        const uint32_t aAh = sb + ((wm + aRow) * SST2 + aK) * 2;
        const uint32_t aAl = aAh + BUF2 * 2;
        const uint32_t aBh = sb + 2 * BUF2 * 2 + ((wn + bRow) * SST2 + bK) * 2;
        const uint32_t aBl = aBh + BUF2 * 2;

        #pragma unroll
        for (int k16 = 0; k16 < 2; k16++) {
            const uint32_t koff = (k16 << 4) * 2;
            uint32_t ah[2][4], al[2][4];
            #pragma unroll
            for (int mt = 0; mt < 2; mt++) {
                const uint32_t moff = (mt << 4) * SST2 * 2;
                ldsm4(ah[mt][0], ah[mt][1], ah[mt][2], ah[mt][3], aAh + moff + koff);
                ldsm4(al[mt][0], al[mt][1], al[mt][2], al[mt][3], aAl + moff + koff);
            }
            #pragma unroll
            for (int p = 0; p < 4; p++) {
                const uint32_t noff = (p << 4) * SST2 * 2;
                uint32_t bh0, bh1, bh2, bh3, bl0, bl1, bl2, bl3;
                ldsm4(bh0, bh1, bh2, bh3, aBh + noff + koff);
                ldsm4(bl0, bl1, bl2, bl3, aBl + noff + koff);
                #pragma unroll
                for (int mt = 0; mt < 2; mt++) {
                    mma16816(acc[mt][2 * p + 0], ah[mt], bh0, bh1);
                    mma16816(acc[mt][2 * p + 1], ah[mt], bh2, bh3);
                    mma16816(acc[mt][2 * p + 0], ah[mt], bl0, bl1);
                    mma16816(acc[mt][2 * p + 1], ah[mt], bl2, bl3);
                    mma16816(acc[mt][2 * p + 0], al[mt], bh0, bh1);
                    mma16816(acc[mt][2 * p + 1], al[mt], bh2, bh3);
                }
            }
        }
        __syncthreads();
    }
    #undef ISSUE_STAGE

    // Epilogue
    const int g = lane >> 2, tq = lane & 3;
    #pragma unroll
    for (int mt = 0; mt < 2; mt++) {
        #pragma unroll
        for (int nt = 0; nt < 8; nt++) {
            const int c = bn + wn + nt * 8 + 2 * tq;
            #pragma unroll
            for (int half = 0; half < 2; half++) {
                const int r = bm + wm + mt * 16 + g + half * 8;
                float2 v;
                v.x = acc[mt][nt][2 * half + 0];
                v.y = acc[mt][nt][2 * half + 1];
                if (MODE == 0) {
                    *(float2*)(Cout + (size_t)r * DD + c) = v;
                } else {
                    const float2 bv = *(const float2*)(g_bqkv + c);
                    v.x += bv.x; v.y += bv.y;
                    const int which = c >> 10;
                    const int cc = c & 1023;
                    const int h = cc >> 6;
                    const size_t idx = ((((size_t)((r >> 11) * HH + h)) * NN
                                        + (r & 2047)) << 6) + (cc & 63);
                    if (which == 0)      *(float2*)(g_q + idx) = v;
                    else if (which == 1) *(float2*)(g_k + idx) = v;
                    else                 hl2_store(v.x, v.y, g_vh + idx, g_vl + idx);
                }
            }
        }
    }
}

// ---------------------------------------------------------------------------
// Kernel 3: per-head LayerNorm over DH=64 -> hi/lo bf16
// ---------------------------------------------------------------------------
template<int WHICH>   // 1 = q (apply scale), 2 = k
__global__ __launch_bounds__(256)
void headln_kernel(const float* __restrict__ w,
                   const float* __restrict__ b,
                   float sc)
{
    const float* base = (WHICH == 1) ? g_q : g_k;
    __nv_bfloat16* oh = (WHICH == 1) ? g_qh : g_kh;
    __nv_bfloat16* ol = (WHICH == 1) ? g_ql : g_kl;
    const int warp = threadIdx.x >> 5;
    const int lane = threadIdx.x & 31;
    const long row = (long)blockIdx.x * 8 + warp;
    const float* p = base + row * DH;

    float2 xv = *(const float2*)(p + lane * 2);
    float sum = xv.x + xv.y;
    float ssq = fmaf(xv.x, xv.x, xv.y * xv.y);
    #pragma unroll
    for (int o = 16; o > 0; o >>= 1) {
        sum += __shfl_xor_sync(0xffffffffu, sum, o);
        ssq += __shfl_xor_sync(0xffffffffu, ssq, o);
    }
    const float mean = sum * (1.0f / DH);
    const float var = ssq * (1.0f / DH) - mean * mean;
    const float rstd = rsqrtf(var + LN_EPS);

    float2 wv = *(const float2*)(w + lane * 2);
    float2 bv = *(const float2*)(b + lane * 2);
    float a = ((xv.x - mean) * rstd * wv.x + bv.x) * sc;
    float c = ((xv.y - mean) * rstd * wv.y + bv.y) * sc;
    hl2_store(a, c, oh + row * DH + lane * 2, ol + row * DH + lane * 2);
}

// ---------------------------------------------------------------------------
// Kernel 4: tensor-core flash attention (HMMA bf16x3 for QK^T and PV)
// grid (16, 16, 4): 128 queries x one (b,h) per CTA; 8 warps x 16 q-rows.
// ---------------------------------------------------------------------------
#define ASTR 72

__global__ __launch_bounds__(256)
void attn_mma_kernel()
{
    __shared__ __align__(16) __nv_bfloat16 sm[4 * 64 * ASTR];  // 36864 B
    __shared__ float mb[64];

    const int tid = threadIdx.x, wid = tid >> 5, lane = tid & 31;
    const int bq = blockIdx.x << 7;
    const int h = blockIdx.y, b = blockIdx.z;
    const size_t head_off = ((size_t)(b * HH + h)) * NN;

    const uint32_t u0 = s2u(sm);
    const uint32_t Kh = u0;
    const uint32_t Kl = u0 + 64 * ASTR * 2;
    const uint32_t Vh = u0 + 2 * 64 * ASTR * 2;
    const uint32_t Vl = u0 + 3 * 64 * ASTR * 2;

    // ldmatrix lane addressing
    const int aRow = (lane & 7) + ((lane & 8) ? 8 : 0);
    const int aK   = (lane & 16) ? 8 : 0;
    const int bRow = (lane & 7) + ((lane & 16) ? 8 : 0);
    const int bK   = (lane & 8) ? 8 : 0;
    const int vRow = (lane & 7) + ((lane & 8) ? 8 : 0);
    const int vCol = (lane & 16) ? 8 : 0;

    // ---- Phase 1: stage Q (128x64 hi/lo) through smem, ldmatrix to regs
    {
        const int r = tid >> 1;
        const int c = (tid & 1) << 5;
        const __nv_bfloat16* sh = g_qh + (head_off + bq + r) * DH + c;
        const __nv_bfloat16* sl = g_ql + (head_off + bq + r) * DH + c;
        #pragma unroll
        for (int i = 0; i < 4; i++) {
            *(uint4*)(sm + r * ASTR + c + i * 8) = *(const uint4*)(sh + i * 8);
            *(uint4*)(sm + 2 * 64 * ASTR + r * ASTR + c + i * 8) = *(const uint4*)(sl + i * 8);
        }
    }
    __syncthreads();

    uint32_t qh[4][4], ql[4][4];
    {
        const uint32_t qb = u0 + ((wid * 16 + aRow) * ASTR + aK) * 2;
        #pragma unroll
        for (int k = 0; k < 4; k++) {
            ldsm4(qh[k][0], qh[k][1], qh[k][2], qh[k][3], qb + (k * 16) * 2);
            ldsm4(ql[k][0], ql[k][1], ql[k][2], ql[k][3],
                  qb + (2 * 64 * ASTR + k * 16) * 2);
        }
    }

    float o[8][4];
    #pragma unroll
    for (int i = 0; i < 8; i++)
        #pragma unroll
        for (int j = 0; j < 4; j++) o[i][j] = 0.0f;
    float m0 = -1e30f, m1 = -1e30f, l0 = 0.0f, l1 = 0.0f;

    const float* mrow = g_maskbias + b * NN;
    const int tq2 = (lane & 3) * 2;

    for (int kt = 0; kt < NN; kt += 64) {
        __syncthreads();
        // load K/V tiles (bf16 hi/lo, pre-split)
        {
            const int r = tid >> 2;
            const int c = (tid & 3) << 4;
            const size_t gidx = (head_off + kt + r) * DH + c;
            const int so = r * ASTR + c;
            #pragma unroll
            for (int i = 0; i < 2; i++) {
                *(uint4*)(sm + so + i * 8)                    = *(const uint4*)(g_kh + gidx + i * 8);
                *(uint4*)(sm + 64 * ASTR + so + i * 8)        = *(const uint4*)(g_kl + gidx + i * 8);
                *(uint4*)(sm + 2 * 64 * ASTR + so + i * 8)    = *(const uint4*)(g_vh + gidx + i * 8);
                *(uint4*)(sm + 3 * 64 * ASTR + so + i * 8)    = *(const uint4*)(g_vl + gidx + i * 8);
            }
            if (tid < 64) mb[tid] = mrow[kt + tid];
        }
        __syncthreads();

        // S = Q K^T  (bf16x3)
        float s[8][4];
        #pragma unroll
        for (int i = 0; i < 8; i++)
            #pragma unroll
            for (int j = 0; j < 4; j++) s[i][j] = 0.0f;

        #pragma unroll
        for (int k = 0; k < 4; k++) {
            #pragma unroll
            for (int p = 0; p < 4; p++) {
                const uint32_t nb = ((p * 16 + bRow) * ASTR + k * 16 + bK) * 2;
                uint32_t bh0, bh1, bh2, bh3, bl0, bl1, bl2, bl3;
                ldsm4(bh0, bh1, bh2, bh3, Kh + nb);
                ldsm4(bl0, bl1, bl2, bl3, Kl + nb);
                mma16816(s[2 * p + 0], qh[k], bh0, bh1);
                mma16816(s[2 * p + 1], qh[k], bh2, bh3);
                mma16816(s[2 * p + 0], qh[k], bl0, bl1);
                mma16816(s[2 * p + 1], qh[k], bl2, bl3);
                mma16816(s[2 * p + 0], ql[k], bh0, bh1);
                mma16816(s[2 * p + 1], ql[k], bh2, bh3);
            }
        }

        // mask + online softmax
        float mx0 = -1e30f, mx1 = -1e30f;
        #pragma unroll
        for (int nt = 0; nt < 8; nt++) {
            const float b0 = mb[nt * 8 + tq2];
            const float b1 = mb[nt * 8 + tq2 + 1];
            s[nt][0] += b0; s[nt][1] += b1;
            s[nt][2] += b0; s[nt][3] += b1;
            mx0 = fmaxf(mx0, fmaxf(s[nt][0], s[nt][1]));
            mx1 = fmaxf(mx1, fmaxf(s[nt][2], s[nt][3]));
        }
        mx0 = fmaxf(mx0, __shfl_xor_sync(0xffffffffu, mx0, 1));
        mx0 = fmaxf(mx0, __shfl_xor_sync(0xffffffffu, mx0, 2));
        mx1 = fmaxf(mx1, __shfl_xor_sync(0xffffffffu, mx1, 1));
        mx1 = fmaxf(mx1, __shfl_xor_sync(0xffffffffu, mx1, 2));
        const float mn0 = fmaxf(m0, mx0), mn1 = fmaxf(m1, mx1);
        const float sc0 = __expf(m0 - mn0), sc1 = __expf(m1 - mn1);
        m0 = mn0; m1 = mn1;
        float ps0 = 0.0f, ps1 = 0.0f;
        #pragma unroll
        for (int nt = 0; nt < 8; nt++) {
            s[nt][0] = __expf(s[nt][0] - m0);
            s[nt][1] = __expf(s[nt][1] - m0);
            s[nt][2] = __expf(s[nt][2] - m1);
            s[nt][3] = __expf(s[nt][3] - m1);
            ps0 += s[nt][0] + s[nt][1];
            ps1 += s[nt][2] + s[nt][3];
        }
        ps0 += __shfl_xor_sync(0xffffffffu, ps0, 1);
        ps0 += __shfl_xor_sync(0xffffffffu, ps0, 2);
        ps1 += __shfl_xor_sync(0xffffffffu, ps1, 1);
        ps1 += __shfl_xor_sync(0xffffffffu, ps1, 2);
        l0 = l0 * sc0 + ps0;
        l1 = l1 * sc1 + ps1;
        #pragma unroll
        for (int nt = 0; nt < 8; nt++) {
            o[nt][0] *= sc0; o[nt][1] *= sc0;
            o[nt][2] *= sc1; o[nt][3] *= sc1;
        }

        // O += P V   (P hi/lo x V hi/lo, 3 passes)
        #pragma unroll
        for (int jj = 0; jj < 4; jj++) {
            uint32_t ph[4], pl[4];
            hl_pack(s[2 * jj][0],     s[2 * jj][1],     ph[0], pl[0]);
            hl_pack(s[2 * jj][2],     s[2 * jj][3],     ph[1], pl[1]);
            hl_pack(s[2 * jj + 1][0], s[2 * jj + 1][1], ph[2], pl[2]);
            hl_pack(s[2 * jj + 1][2], s[2 * jj + 1][3], ph[3], pl[3]);
            #pragma unroll
            for (int p = 0; p < 4; p++) {
                const uint32_t off = ((jj * 16 + vRow) * ASTR + p * 16 + vCol) * 2;
                uint32_t bh0, bh1, bh2, bh3, bl0, bl1, bl2, bl3;
                ldsm4t(bh0, bh1, bh2, bh3, Vh + off);
                ldsm4t(bl0, bl1, bl2, bl3, Vl + off);
                mma16816(o[2 * p + 0], ph, bh0, bh1);
                mma16816(o[2 * p + 1], ph, bh2, bh3);
                mma16816(o[2 * p + 0], ph, bl0, bl1);
                mma16816(o[2 * p + 1], ph, bl2, bl3);
                mma16816(o[2 * p + 0], pl, bh0, bh1);
                mma16816(o[2 * p + 1], pl, bh2, bh3);
            }
        }
    }

    // epilogue -> g_ao hi/lo   [b, n, h*64+dh]
    const float inv0 = 1.0f / l0, inv1 = 1.0f / l1;
    const int g = lane >> 2;
    const int q0 = bq + wid * 16 + g;
    const size_t ob = ((size_t)(b * NN) + q0) * DD + h * DH;
    #pragma unroll
    for (int nt = 0; nt < 8; nt++) {
        const int dh = nt * 8 + tq2;
        hl2_store(o[nt][0] * inv0, o[nt][1] * inv0, g_ao_hi + ob + dh, g_ao_lo + ob + dh);
        hl2_store(o[nt][2] * inv1, o[nt][3] * inv1,
                  g_ao_hi + ob + 8 * DD + dh, g_ao_lo + ob + 8 * DD + dh);
    }
}

// ---------------------------------------------------------------------------
// Launch
// ---------------------------------------------------------------------------
extern "C" void kernel_launch(void* const* d_in, const int* in_sizes, int n_in,
                              void* d_out, int out_size)
{
    const float* x       = (const float*)d_in[0];
    const void*  mask    = (const void*)d_in[1];
    const float* norm_w  = (const float*)d_in[2];
    const float* norm_b  = (const float*)d_in[3];
    const float* qn_w    = (const float*)d_in[4];
    const float* qn_b    = (const float*)d_in[5];
    const float* kn_w    = (const float*)d_in[6];
    const float* kn_b    = (const float*)d_in[7];
    const float* Wq      = (const float*)d_in[8];
    const float* bq      = (const float*)d_in[9];
    const float* Wk      = (const float*)d_in[10];
    const float* bk      = (const float*)d_in[11];
    const float* Wv      = (const float*)d_in[12];
    const float* bv      = (const float*)d_in[13];
    const float* Wo      = (const float*)d_in[14];
    float* out = (float*)d_out;

    static bool attr_done = false;
    if (!attr_done) {
        cudaFuncSetAttribute(gemm_mma2<0>, cudaFuncAttributeMaxDynamicSharedMemorySize, GEMM_SMEM2);
        cudaFuncSetAttribute(gemm_mma2<4>, cudaFuncAttributeMaxDynamicSharedMemorySize, GEMM_SMEM2);
        attr_done = true;
    }

    // 0. Mask -> float bias; bias concat; W -> hi/lo bf16
    prep_kernel<<<1, 256>>>(mask, bq, bk, bv);
    wconv_kernel<<<1024, 256>>>(Wq, 0);
    wconv_kernel<<<1024, 256>>>(Wk, 1);
    wconv_kernel<<<1024, 256>>>(Wv, 2);
    wconv_kernel<<<1024, 256>>>(Wo, 3);

    // 1. LN(x) -> hi/lo bf16
    ln_x_kernel<<<BN, 256>>>(x, norm_w, norm_b);

    // 2. Fused QKV projection (cp.async pipelined HMMA bf16x3)
    gemm_mma2<4><<<dim3(3 * DD / 128, BN / 128), 256, GEMM_SMEM2>>>(nullptr);

    // 3. Per-head LN -> q/k hi/lo bf16 (q scaled by DH^-0.5)
    const int ln_blocks = (BB * HH * NN) / 8;
    headln_kernel<1><<<ln_blocks, 256>>>(qn_w, qn_b, 0.125f);
    headln_kernel<2><<<ln_blocks, 256>>>(kn_w, kn_b, 1.0f);

    // 4. Tensor-core flash attention -> g_ao hi/lo
    attn_mma_kernel<<<dim3(NN / 128, HH, BB), 256>>>();

    // 5. Output projection -> d_out
    gemm_mma2<0><<<dim3(DD / 128, BN / 128), 256, GEMM_SMEM2>>>(out);
}